// round 3
// baseline (speedup 1.0000x reference)
#include <cuda_runtime.h>

#define TPB   1024
#define NB    128
#define NV    128000
#define NV4   (NV/4)
#define NL    200
#define HSZ   1024
#define HMASK 1023
#define NBINS 4096
#define CAP   2048

__device__ __forceinline__ float hlookup(int idx, const int* hkey, const float* hval) {
    unsigned h = ((unsigned)idx * 2654435761u) >> 22;
    int k = hkey[h];
    while (k >= 0) {
        if (k == idx) return hval[h];
        h = (h + 1) & HMASK;
        k = hkey[h];
    }
    return 0.0f;
}

__global__ __launch_bounds__(TPB, 1)
void sampler_kernel(const float* __restrict__ logits,
                    const int* __restrict__ toks,
                    const float* __restrict__ presp,
                    const float* __restrict__ freqp,
                    const float* __restrict__ temps,
                    const float* __restrict__ topps,
                    const int* __restrict__ topks,
                    float* __restrict__ out)
{
    __shared__ int   s_hkey[HSZ];
    __shared__ float s_hval[HSZ];
    __shared__ unsigned s_hist[NBINS];              // later reused as 2x2048 float scan buffers
    __shared__ unsigned long long s_cand[CAP];
    __shared__ float s_redf[32];
    __shared__ unsigned s_redu[32];
    __shared__ float s_M, s_Z, s_S;
    __shared__ unsigned s_cnt, s_bstar, s_C, s_m, s_found;
    __shared__ unsigned long long s_cut;

    const int tid  = threadIdx.x;
    const int lane = tid & 31;
    const int wid  = tid >> 5;
    const int b    = blockIdx.x;

    const float invT = 1.0f / temps[b];
    const float fpen = freqp[b];
    const float ppen = presp[b];
    const int   Ksel = topks[b];
    const unsigned K = (unsigned)Ksel;

    // ---- init smem ----
    for (int i = tid; i < HSZ; i += TPB) { s_hkey[i] = -1; ((int*)s_hval)[i] = 0; }
    if (tid == 0) s_cnt = 0;
    __syncthreads();

    // ---- build penalty hash (token -> f*count + p) ----
    if (tid < NL) {
        int tok = toks[(size_t)b * NL + tid];
        unsigned h = ((unsigned)tok * 2654435761u) >> 22;
        for (;;) {
            int prev = atomicCAS(&s_hkey[h], -1, tok);
            if (prev == -1 || prev == tok) { atomicAdd((int*)&s_hval[h], 1); break; }
            h = (h + 1) & HMASK;
        }
    }
    __syncthreads();
    for (int i = tid; i < HSZ; i += TPB) {
        if (s_hkey[i] >= 0) {
            int c = ((int*)s_hval)[i];
            s_hval[i] = fpen * (float)c + ppen;
        }
    }
    __syncthreads();

    const float4* lg4 = reinterpret_cast<const float4*>(logits + (size_t)b * NV);

    // ---- Pass 1: max of base logits (penalties only lower values; softmax shift just needs >= true max) ----
    float mx = -3.4e38f;
    for (int v = tid; v < NV4; v += TPB) {
        float4 x = lg4[v];
        mx = fmaxf(mx, fmaxf(fmaxf(x.x, x.y), fmaxf(x.z, x.w)));
    }
    for (int o = 16; o; o >>= 1) mx = fmaxf(mx, __shfl_xor_sync(0xffffffffu, mx, o));
    if (lane == 0) s_redf[wid] = mx;
    __syncthreads();
    if (wid == 0) {
        float r = s_redf[lane];
        for (int o = 16; o; o >>= 1) r = fmaxf(r, __shfl_xor_sync(0xffffffffu, r, o));
        if (lane == 0) s_M = r;
    }
    __syncthreads();
    mx = s_M;
    const float M = mx * invT;             // shift in e-space

    // ---- Pass 2: Z (base + fixups) and adaptive tail histogram in raw-x space ----
    float zp = 0.0f;
    float window = 3.2f;
    float hsc = 0.0f;
    unsigned found = 0;
    for (int att = 0; att < 4 && !found; att++) {
        hsc = (float)NBINS / window;
        for (int i = tid; i < NBINS; i += TPB) s_hist[i] = 0;
        if (tid == 0) s_found = 0;
        __syncthreads();

        for (int v = tid; v < NV4; v += TPB) {
            float4 x = lg4[v];
            float xs[4] = {x.x, x.y, x.z, x.w};
            #pragma unroll
            for (int c = 0; c < 4; c++) {
                if (att == 0) zp += __expf(xs[c] * invT - M);
                float ds = (mx - xs[c]) * hsc;
                if (ds < (float)NBINS) atomicAdd(&s_hist[(int)ds], 1u);
            }
        }
        for (int i = tid; i < HSZ; i += TPB) {
            int tok = s_hkey[i];
            if (tok >= 0) {
                float x = logits[(size_t)b * NV + tok];
                float a = s_hval[i];
                if (att == 0)
                    zp += __expf((x - a) * invT - M) - __expf(x * invT - M);
                float ds0 = (mx - x) * hsc;
                float ds1 = (mx - x + a) * hsc;
                if (ds0 < (float)NBINS) atomicSub(&s_hist[(int)ds0], 1u);
                if (ds1 < (float)NBINS) atomicAdd(&s_hist[(int)ds1], 1u);
            }
        }
        __syncthreads();

        // selection: smallest bin prefix holding >= K elements
        unsigned c0 = s_hist[tid*4+0], c1 = s_hist[tid*4+1], c2 = s_hist[tid*4+2], c3 = s_hist[tid*4+3];
        unsigned i0 = c0, i1 = i0 + c1, i2 = i1 + c2, i3 = i2 + c3;
        unsigned tsum = i3;
        unsigned incl = tsum;
        for (int o = 1; o < 32; o <<= 1) { unsigned t = __shfl_up_sync(0xffffffffu, incl, o); if (lane >= o) incl += t; }
        if (lane == 31) s_redu[wid] = incl;
        __syncthreads();
        if (wid == 0) {
            unsigned w  = s_redu[lane];
            unsigned wi = w;
            for (int o = 1; o < 32; o <<= 1) { unsigned t = __shfl_up_sync(0xffffffffu, wi, o); if (lane >= o) wi += t; }
            s_redu[lane] = wi - w;         // exclusive warp offset
        }
        __syncthreads();
        unsigned start = (incl - tsum) + s_redu[wid];
        if (start < K && start + tsum >= K) {   // unique crossing thread
            unsigned bsel, cc;
            if      (start + i0 >= K) { bsel = 0; cc = start + i0; }
            else if (start + i1 >= K) { bsel = 1; cc = start + i1; }
            else if (start + i2 >= K) { bsel = 2; cc = start + i2; }
            else                      { bsel = 3; cc = start + i3; }
            s_bstar = (unsigned)(tid*4) + bsel; s_C = cc; s_found = 1;
        }
        __syncthreads();
        found = s_found;
        if (!found) window *= 2.0f;        // rare: row max unusually high; widen and retry
    }

    // Z reduction
    for (int o = 16; o; o >>= 1) zp += __shfl_xor_sync(0xffffffffu, zp, o);
    if (lane == 0) s_redf[wid] = zp;
    __syncthreads();
    if (wid == 0) {
        float r = s_redf[lane];
        for (int o = 16; o; o >>= 1) r += __shfl_xor_sync(0xffffffffu, r, o);
        if (lane == 0) s_Z = r;
    }
    __syncthreads();
    const float invZ = 1.0f / s_Z;
    const float xcut = (float)(s_bstar + 1) / hsc;   // candidate iff (mx - x_pen) * hsc < bstar+1
    unsigned C = min(s_C, (unsigned)CAP);

    // ---- Pass 3: collect candidates (prob_bits<<32 | ~idx  -> stable desc order) ----
    for (int v = tid; v < NV4; v += TPB) {
        float4 x = lg4[v];
        int base = v * 4;
        float xs[4] = {x.x, x.y, x.z, x.w};
        #pragma unroll
        for (int c = 0; c < 4; c++) {
            if (mx - xs[c] < xcut) {       // base prefilter (penalty only pushes further out)
                int idx = base + c;
                float a = hlookup(idx, s_hkey, s_hval);
                if (mx - xs[c] + a < xcut) {
                    float q = __expf((xs[c] - a) * invT - M) * invZ;
                    unsigned pos = atomicAdd(&s_cnt, 1u);
                    if (pos < CAP)
                        s_cand[pos] = ((unsigned long long)__float_as_uint(q) << 32)
                                      | (unsigned)(~(unsigned)idx);
                }
            }
        }
    }
    __syncthreads();

    // ---- pad to pow2 and bitonic sort descending ----
    unsigned P = 32; while (P < C) P <<= 1;
    for (unsigned i = tid; i < P; i += TPB) if (i >= C) s_cand[i] = 0ull;
    __syncthreads();
    for (unsigned k = 2; k <= P; k <<= 1) {
        for (unsigned j = k >> 1; j > 0; j >>= 1) {
            for (unsigned i = tid; i < P; i += TPB) {
                unsigned l = i ^ j;
                if (l > i) {
                    unsigned long long a = s_cand[i], bb = s_cand[l];
                    bool desc = ((i & k) == 0);
                    if (desc ? (a < bb) : (a > bb)) { s_cand[i] = bb; s_cand[l] = a; }
                }
            }
            __syncthreads();
        }
    }

    // ---- inclusive scan of candidate probs ----
    float* A  = (float*)s_hist;
    float* Bf = A + 2048;
    for (unsigned i = tid; i < P; i += TPB)
        A[i] = (i < C) ? __uint_as_float((unsigned)(s_cand[i] >> 32)) : 0.0f;
    __syncthreads();
    float* src = A; float* dst = Bf;
    for (unsigned off = 1; off < P; off <<= 1) {
        for (unsigned i = tid; i < P; i += TPB) {
            float v2 = src[i];
            if (i >= off) v2 += src[i - off];
            dst[i] = v2;
        }
        __syncthreads();
        float* t = src; src = dst; dst = t;
    }

    // ---- kept prefix length m, kept sum S, cut key ----
    const float tp = topps[b];
    int mloc = 0;
    for (unsigned i = tid; i < P; i += TPB) {
        if (i < C && (int)i < Ksel) {
            float inc = src[i];
            float q   = __uint_as_float((unsigned)(s_cand[i] >> 32));
            if (inc - q <= tp) mloc++;     // kept iff exclusive cumsum <= top_p and rank < K
        }
    }
    for (int o = 16; o; o >>= 1) mloc += __shfl_xor_sync(0xffffffffu, mloc, o);
    if (lane == 0) s_redu[wid] = (unsigned)mloc;
    __syncthreads();
    if (wid == 0) {
        unsigned r = s_redu[lane];
        for (int o = 16; o; o >>= 1) r += __shfl_xor_sync(0xffffffffu, r, o);
        if (lane == 0) s_m = r;
    }
    __syncthreads();
    unsigned m = s_m; if (m == 0) m = 1;
    if (tid == 0) { s_S = src[m-1]; s_cut = s_cand[m-1]; }
    __syncthreads();
    const float invS = 1.0f / s_S;
    const unsigned long long cut = s_cut;

    // ---- Pass 4: write output ----
    float4* o4 = reinterpret_cast<float4*>(out + (size_t)b * NV);
    for (int v = tid; v < NV4; v += TPB) {
        float4 x = lg4[v];
        int base = v * 4;
        float xs[4] = {x.x, x.y, x.z, x.w};
        float rs[4];
        #pragma unroll
        for (int c = 0; c < 4; c++) {
            float rv = 0.0f;
            if (mx - xs[c] < xcut) {
                int idx = base + c;
                float a = hlookup(idx, s_hkey, s_hval);
                if (mx - xs[c] + a < xcut) {
                    float q = __expf((xs[c] - a) * invT - M) * invZ;
                    unsigned long long key = ((unsigned long long)__float_as_uint(q) << 32)
                                             | (unsigned)(~(unsigned)idx);
                    if (key >= cut) rv = q * invS;
                }
            }
            rs[c] = rv;
        }
        float4 r4; r4.x = rs[0]; r4.y = rs[1]; r4.z = rs[2]; r4.w = rs[3];
        o4[v] = r4;
    }
}

extern "C" void kernel_launch(void* const* d_in, const int* in_sizes, int n_in,
                              void* d_out, int out_size) {
    const float* logits = (const float*)d_in[0];
    const int*   toks   = (const int*)d_in[1];
    const float* pres   = (const float*)d_in[2];
    const float* freq   = (const float*)d_in[3];
    const float* temps  = (const float*)d_in[4];
    const float* topps  = (const float*)d_in[5];
    const int*   topks  = (const int*)d_in[6];
    sampler_kernel<<<NB, TPB>>>(logits, toks, pres, freq, temps, topps, topks, (float*)d_out);
}

// round 4
// speedup vs baseline: 1.2256x; 1.2256x over previous
#include <cuda_runtime.h>

#define TPB   1024
#define NB    128
#define NV    128000
#define NV4   (NV/4)
#define NL    200
#define HSZ   512
#define HMASK 511
#define NBINS 4096
#define CAP   3072
#define SCAP  2048
#define HIW   7.0f
#define LB0   2.1f

__device__ __forceinline__ float hlookup(int idx, const int* hkey, const float* hval) {
    unsigned h = ((unsigned)idx * 2654435761u) >> 23;
    int k = hkey[h];
    while (k >= 0) {
        if (k == idx) return hval[h];
        h = (h + 1) & HMASK;
        k = hkey[h];
    }
    return 0.0f;
}

__global__ __launch_bounds__(TPB, 1)
void sampler_kernel(const float* __restrict__ logits,
                    const int* __restrict__ toks,
                    const float* __restrict__ presp,
                    const float* __restrict__ freqp,
                    const float* __restrict__ temps,
                    const float* __restrict__ topps,
                    const int* __restrict__ topks,
                    float* __restrict__ out)
{
    __shared__ int   s_hkey[HSZ];
    __shared__ float s_hval[HSZ];
    __shared__ unsigned long long s_sortbuf[SCAP];   // aliases 4096-bin histogram
    __shared__ unsigned long long s_cand[CAP];       // aliases 2x2048 float scan buffers
    __shared__ float s_redf[32];
    __shared__ unsigned s_redu[32];
    __shared__ float s_Z, s_S;
    __shared__ unsigned s_cnt, s_cc, s_bstar, s_C, s_m, s_found;

    unsigned* s_hist = (unsigned*)s_sortbuf;

    const int tid  = threadIdx.x;
    const int lane = tid & 31;
    const int wid  = tid >> 5;
    const int b    = blockIdx.x;

    const float invT = 1.0f / temps[b];
    const float fpen = freqp[b];
    const float ppen = presp[b];
    const int   Ksel = topks[b];
    const unsigned K = (unsigned)Ksel;

    // ---- penalty hash: token -> f*count + p ----
    for (int i = tid; i < HSZ; i += TPB) { s_hkey[i] = -1; ((int*)s_hval)[i] = 0; }
    __syncthreads();
    if (tid < NL) {
        int tok = toks[(size_t)b * NL + tid];
        unsigned h = ((unsigned)tok * 2654435761u) >> 23;
        for (;;) {
            int prev = atomicCAS(&s_hkey[h], -1, tok);
            if (prev == -1 || prev == tok) { atomicAdd((int*)&s_hval[h], 1); break; }
            h = (h + 1) & HMASK;
        }
    }
    __syncthreads();
    for (int i = tid; i < HSZ; i += TPB) {
        if (s_hkey[i] >= 0) {
            int c = ((int*)s_hval)[i];
            s_hval[i] = fpen * (float)c + ppen;
        }
    }
    __syncthreads();

    const float4* lg4 = reinterpret_cast<const float4*>(logits + (size_t)b * NV);

    // ---- fused pass: Z (base) + penalized tail histogram + candidate collect ----
    float zp = 0.0f;
    float LBc = LB0;
    float hsc = 0.0f;
    unsigned found = 0;
    for (int att = 0; att < 4 && !found; att++) {
        hsc = (float)NBINS / (HIW - LBc);
        for (int i = tid; i < NBINS; i += TPB) s_hist[i] = 0;
        if (tid == 0) { s_cnt = 0; s_found = 0; }
        zp = 0.0f;
        __syncthreads();

        for (int v = tid; v < NV4; v += TPB) {
            float4 x = lg4[v];
            int base = v * 4;
            float xs[4] = {x.x, x.y, x.z, x.w};
            #pragma unroll
            for (int c = 0; c < 4; c++) {
                float xv = xs[c];
                zp += __expf(xv * invT);
                if (xv > LBc) {
                    float a  = hlookup(base + c, s_hkey, s_hval);
                    float xp = xv - a;
                    if (xp > LBc) {
                        float ds = (HIW - xp) * hsc;
                        int ids = (int)ds; ids = max(ids, 0);
                        atomicAdd(&s_hist[ids], 1u);
                        unsigned pos = atomicAdd(&s_cnt, 1u);
                        if (pos < CAP)
                            s_cand[pos] = ((unsigned long long)__float_as_uint(xp) << 32)
                                          | (unsigned)(~(unsigned)(base + c));
                    }
                }
            }
        }
        __syncthreads();

        // selection: smallest bin prefix holding >= K elements
        unsigned c0 = s_hist[tid*4+0], c1 = s_hist[tid*4+1], c2 = s_hist[tid*4+2], c3 = s_hist[tid*4+3];
        unsigned i0 = c0, i1 = i0 + c1, i2 = i1 + c2, i3 = i2 + c3;
        unsigned tsum = i3;
        unsigned incl = tsum;
        for (int o = 1; o < 32; o <<= 1) { unsigned t = __shfl_up_sync(0xffffffffu, incl, o); if (lane >= o) incl += t; }
        if (lane == 31) s_redu[wid] = incl;
        __syncthreads();
        if (wid == 0) {
            unsigned w  = s_redu[lane];
            unsigned wi = w;
            for (int o = 1; o < 32; o <<= 1) { unsigned t = __shfl_up_sync(0xffffffffu, wi, o); if (lane >= o) wi += t; }
            s_redu[lane] = wi - w;
        }
        __syncthreads();
        unsigned start = (incl - tsum) + s_redu[wid];
        if (start < K && start + tsum >= K) {
            unsigned bsel, cc;
            if      (start + i0 >= K) { bsel = 0; cc = start + i0; }
            else if (start + i1 >= K) { bsel = 1; cc = start + i1; }
            else if (start + i2 >= K) { bsel = 2; cc = start + i2; }
            else                      { bsel = 3; cc = start + i3; }
            s_bstar = (unsigned)(tid*4) + bsel; s_C = cc; s_found = 1;
        }
        if (att == 3 && tid == TPB-1 && start + tsum < K) { s_bstar = NBINS-1; s_C = start + tsum; s_found = 1; }
        __syncthreads();
        found = s_found;
        if (!found) { LBc -= 5.0f; __syncthreads(); }
    }

    // ---- Z fixup for penalized tokens, then reduce ----
    for (int i = tid; i < HSZ; i += TPB) {
        int tok = s_hkey[i];
        if (tok >= 0) {
            float x = logits[(size_t)b * NV + tok];
            float a = s_hval[i];
            zp += __expf((x - a) * invT) - __expf(x * invT);
        }
    }
    for (int o = 16; o; o >>= 1) zp += __shfl_xor_sync(0xffffffffu, zp, o);
    if (lane == 0) s_redf[wid] = zp;
    __syncthreads();
    if (wid == 0) {
        float r = s_redf[lane];
        for (int o = 16; o; o >>= 1) r += __shfl_xor_sync(0xffffffffu, r, o);
        if (lane == 0) s_Z = r;
    }
    __syncthreads();
    const float invZ = 1.0f / s_Z;
    const unsigned bstar = s_bstar;
    unsigned total = s_cnt;

    // ---- overflow fallback: recollect only candidates within selected bins ----
    if (total > CAP) {
        if (tid == 0) s_cnt = 0;
        __syncthreads();
        for (int v = tid; v < NV4; v += TPB) {
            float4 x = lg4[v];
            int base = v * 4;
            float xs[4] = {x.x, x.y, x.z, x.w};
            #pragma unroll
            for (int c = 0; c < 4; c++) {
                float xv = xs[c];
                if (xv > LBc) {
                    float a  = hlookup(base + c, s_hkey, s_hval);
                    float xp = xv - a;
                    if (xp > LBc) {
                        float ds = (HIW - xp) * hsc;
                        int ids = (int)ds; ids = max(ids, 0);
                        if ((unsigned)ids <= bstar) {
                            unsigned pos = atomicAdd(&s_cnt, 1u);
                            if (pos < CAP)
                                s_cand[pos] = ((unsigned long long)__float_as_uint(xp) << 32)
                                              | (unsigned)(~(unsigned)(base + c));
                        }
                    }
                }
            }
        }
        __syncthreads();
        total = min(s_cnt, (unsigned)CAP);
    }

    // ---- compact candidates into sort buffer (hist no longer needed) ----
    if (tid == 0) s_cc = 0;
    __syncthreads();
    for (unsigned i = tid; i < total; i += TPB) {
        unsigned long long key = s_cand[i];
        float xp = __uint_as_float((unsigned)(key >> 32));
        float ds = (HIW - xp) * hsc;
        int ids = (int)ds; ids = max(ids, 0);
        if ((unsigned)ids <= bstar) {
            unsigned pos = atomicAdd(&s_cc, 1u);
            if (pos < SCAP) s_sortbuf[pos] = key;
        }
    }

    // ---- zero-fill output now; HBM writes drain under the sort ----
    {
        float4 z4; z4.x = 0.f; z4.y = 0.f; z4.z = 0.f; z4.w = 0.f;
        float4* o4 = reinterpret_cast<float4*>(out + (size_t)b * NV);
        for (int v = tid; v < NV4; v += TPB) o4[v] = z4;
    }
    __syncthreads();
    const unsigned C = min(s_cc, (unsigned)SCAP);

    // ---- bitonic sort descending (pad to pow2) ----
    unsigned P = 32; while (P < C) P <<= 1;
    for (unsigned i = tid; i < P; i += TPB) if (i >= C) s_sortbuf[i] = 0ull;
    __syncthreads();
    for (unsigned k = 2; k <= P; k <<= 1) {
        for (unsigned j = k >> 1; j > 0; j >>= 1) {
            for (unsigned i = tid; i < P; i += TPB) {
                unsigned l = i ^ j;
                if (l > i) {
                    unsigned long long a = s_sortbuf[i], bb = s_sortbuf[l];
                    bool desc = ((i & k) == 0);
                    if (desc ? (a < bb) : (a > bb)) { s_sortbuf[i] = bb; s_sortbuf[l] = a; }
                }
            }
            __syncthreads();
        }
    }

    // ---- probs + inclusive scan (scan buffers alias s_cand) ----
    float* A  = (float*)s_cand;
    float* Bf = A + SCAP;
    for (unsigned i = tid; i < P; i += TPB) {
        float q = 0.0f;
        if (i < C) {
            float xp = __uint_as_float((unsigned)(s_sortbuf[i] >> 32));
            q = __expf(xp * invT) * invZ;
        }
        A[i] = q;
    }
    __syncthreads();
    float* src = A; float* dst = Bf;
    for (unsigned off = 1; off < P; off <<= 1) {
        for (unsigned i = tid; i < P; i += TPB) {
            float v2 = src[i];
            if (i >= off) v2 += src[i - off];
            dst[i] = v2;
        }
        __syncthreads();
        float* t = src; src = dst; dst = t;
    }

    // ---- kept prefix length m, kept sum S ----
    const float tp = topps[b];
    int mloc = 0;
    for (unsigned i = tid; i < P; i += TPB) {
        if (i < C && (int)i < Ksel) {
            float xp = __uint_as_float((unsigned)(s_sortbuf[i] >> 32));
            float q  = __expf(xp * invT) * invZ;
            if (src[i] - q <= tp) mloc++;      // exclusive cumsum <= top_p
        }
    }
    for (int o = 16; o; o >>= 1) mloc += __shfl_xor_sync(0xffffffffu, mloc, o);
    if (lane == 0) s_redu[wid] = (unsigned)mloc;
    __syncthreads();
    if (wid == 0) {
        unsigned r = s_redu[lane];
        for (int o = 16; o; o >>= 1) r += __shfl_xor_sync(0xffffffffu, r, o);
        if (lane == 0) s_m = r;
    }
    __syncthreads();
    unsigned m = s_m; if (m == 0) m = 1;
    if (tid == 0) s_S = src[m-1];
    __syncthreads();
    const float invS = 1.0f / s_S;

    // ---- scatter kept probs (zero-fill already ordered by prior barriers) ----
    for (unsigned i = tid; i < m; i += TPB) {
        unsigned long long key = s_sortbuf[i];
        unsigned idx = ~(unsigned)key;
        float xp = __uint_as_float((unsigned)(key >> 32));
        float q  = __expf(xp * invT) * invZ;
        out[(size_t)b * NV + idx] = q * invS;
    }
}

extern "C" void kernel_launch(void* const* d_in, const int* in_sizes, int n_in,
                              void* d_out, int out_size) {
    const float* logits = (const float*)d_in[0];
    const int*   toks   = (const int*)d_in[1];
    const float* pres   = (const float*)d_in[2];
    const float* freq   = (const float*)d_in[3];
    const float* temps  = (const float*)d_in[4];
    const float* topps  = (const float*)d_in[5];
    const int*   topks  = (const int*)d_in[6];
    sampler_kernel<<<NB, TPB>>>(logits, toks, pres, freq, temps, topps, topks, (float*)d_out);
}

// round 6
// speedup vs baseline: 1.6257x; 1.3264x over previous
#include <cuda_runtime.h>

#define TPB   1024
#define NB    128
#define NV    128000
#define NV4   (NV/4)
#define NL    200
#define HSZ   512
#define HMASK 511
#define NBINS 4096
#define CAP   2560
#define GCAP  512
#define HIW   7.0f
#define LB0   2.1f

__device__ __forceinline__ float hlookup(int idx, const int* hkey, const float* hval) {
    unsigned h = ((unsigned)idx * 2654435761u) >> 23;
    int k = hkey[h];
    while (k >= 0) {
        if (k == idx) return hval[h];
        h = (h + 1) & HMASK;
        k = hkey[h];
    }
    return 0.0f;
}

__global__ __launch_bounds__(TPB, 1)
void sampler_kernel(const float* __restrict__ logits,
                    const int* __restrict__ toks,
                    const float* __restrict__ presp,
                    const float* __restrict__ freqp,
                    const float* __restrict__ temps,
                    const float* __restrict__ topps,
                    const int* __restrict__ topks,
                    float* __restrict__ out)
{
    __shared__ int   s_hkey[HSZ];
    __shared__ float s_hval[HSZ];
    __shared__ unsigned long long s_cand[CAP];
    __shared__ unsigned s_hist[NBINS];                 // reused as float w-hist in stage 2
    __shared__ unsigned long long s_gath[GCAP];
    __shared__ float s_redf[32];
    __shared__ unsigned s_redu[32];
    __shared__ float s_Z, s_WexclK, s_WexclP, s_Wtot, s_S;
    __shared__ unsigned s_cnt, s_gcnt, s_bK, s_bP, s_CntB;
    __shared__ unsigned long long s_cut;

    const int tid  = threadIdx.x;
    const int lane = tid & 31;
    const int wid  = tid >> 5;
    const int b    = blockIdx.x;

    const float invT = 1.0f / temps[b];
    const float fpen = freqp[b];
    const float ppen = presp[b];
    const float tp   = topps[b];
    const int   Ksel = topks[b];
    const unsigned K = (unsigned)Ksel;

    // ---- penalty hash: token -> f*count + p ----
    for (int i = tid; i < HSZ; i += TPB) { s_hkey[i] = -1; ((int*)s_hval)[i] = 0; }
    __syncthreads();
    if (tid < NL) {
        int tok = toks[(size_t)b * NL + tid];
        unsigned h = ((unsigned)tok * 2654435761u) >> 23;
        for (;;) {
            int prev = atomicCAS(&s_hkey[h], -1, tok);
            if (prev == -1 || prev == tok) { atomicAdd((int*)&s_hval[h], 1); break; }
            h = (h + 1) & HMASK;
        }
    }
    __syncthreads();
    for (int i = tid; i < HSZ; i += TPB) {
        if (s_hkey[i] >= 0) {
            int c = ((int*)s_hval)[i];
            s_hval[i] = fpen * (float)c + ppen;
        }
    }
    __syncthreads();

    const float4* lg4 = reinterpret_cast<const float4*>(logits + (size_t)b * NV);
    float4* o4 = reinterpret_cast<float4*>(out + (size_t)b * NV);
    const float4 z4 = make_float4(0.f, 0.f, 0.f, 0.f);

    // ---- pass 1 (with rare retries): Z + zero-fill + candidate collect + count hist ----
    float LB = LB0;
    float hsc = 0.0f;
    float zp = 0.0f;
    unsigned cntEff = 0;
    for (int att = 0; att < 4; att++) {
        hsc = (float)NBINS / (HIW - LB);
        for (int i = tid; i < NBINS; i += TPB) s_hist[i] = 0;
        if (tid == 0) s_cnt = 0;
        zp = 0.0f;
        __syncthreads();

        for (int v = tid; v < NV4; v += TPB) {
            float4 x = lg4[v];
            if (att == 0) o4[v] = z4;            // zero-fill fused into the first read pass
            int base = v * 4;
            float xs[4] = {x.x, x.y, x.z, x.w};
            #pragma unroll
            for (int c = 0; c < 4; c++) {
                float xv = xs[c];
                zp += __expf(xv * invT);
                if (xv > LB) {
                    float a  = hlookup(base + c, s_hkey, s_hval);
                    float xp = xv - a;
                    if (xp > LB) {
                        int ids = (int)((HIW - xp) * hsc);
                        ids = min(max(ids, 0), NBINS - 1);
                        atomicAdd(&s_hist[ids], 1u);
                        unsigned pos = atomicAdd(&s_cnt, 1u);
                        if (pos < CAP)
                            s_cand[pos] = ((unsigned long long)__float_as_uint(xp) << 32)
                                          | (unsigned)(~(unsigned)(base + c));
                    }
                }
            }
        }
        __syncthreads();
        unsigned cnt = s_cnt;
        if (cnt >= K && cnt <= CAP) { cntEff = cnt; break; }
        if (cnt < K) {                           // far too few: widen (shouldn't happen)
            if (att < 3) { LB -= 1.0f; continue; }
            cntEff = min(cnt, (unsigned)CAP); break;
        }
        // overflow: find bin prefix holding >= K via hist, recollect filtered (L2-resident)
        if (tid == 0) s_bK = NBINS;
        __syncthreads();
        {
            unsigned c0 = s_hist[tid*4+0], c1 = s_hist[tid*4+1], c2 = s_hist[tid*4+2], c3 = s_hist[tid*4+3];
            unsigned i0 = c0, i1 = i0+c1, i2 = i1+c2, i3 = i2+c3;
            unsigned tsum = i3, incl = tsum;
            for (int o = 1; o < 32; o <<= 1) { unsigned t = __shfl_up_sync(0xffffffffu, incl, o); if (lane >= o) incl += t; }
            if (lane == 31) s_redu[wid] = incl;
            __syncthreads();
            if (wid == 0) {
                unsigned w = s_redu[lane], wi = w;
                for (int o = 1; o < 32; o <<= 1) { unsigned t = __shfl_up_sync(0xffffffffu, wi, o); if (lane >= o) wi += t; }
                s_redu[lane] = wi - w;
            }
            __syncthreads();
            unsigned start = (incl - tsum) + s_redu[wid];
            if (start < K && start + tsum >= K) {
                if      (start + i0 >= K) s_bK = tid*4+0;
                else if (start + i1 >= K) s_bK = tid*4+1;
                else if (start + i2 >= K) s_bK = tid*4+2;
                else                      s_bK = tid*4+3;
            }
        }
        __syncthreads();
        unsigned bstar = s_bK;
        if (tid == 0) s_cnt = 0;
        __syncthreads();
        for (int v = tid; v < NV4; v += TPB) {
            float4 x = lg4[v];
            int base = v * 4;
            float xs[4] = {x.x, x.y, x.z, x.w};
            #pragma unroll
            for (int c = 0; c < 4; c++) {
                float xv = xs[c];
                if (xv > LB) {
                    float a  = hlookup(base + c, s_hkey, s_hval);
                    float xp = xv - a;
                    if (xp > LB) {
                        int ids = (int)((HIW - xp) * hsc);
                        ids = min(max(ids, 0), NBINS - 1);
                        if ((unsigned)ids <= bstar) {
                            unsigned pos = atomicAdd(&s_cnt, 1u);
                            if (pos < CAP)
                                s_cand[pos] = ((unsigned long long)__float_as_uint(xp) << 32)
                                              | (unsigned)(~(unsigned)(base + c));
                        }
                    }
                }
            }
        }
        __syncthreads();
        cntEff = min(s_cnt, (unsigned)CAP);
        break;
    }

    // ---- Z fixup (penalized tokens) + reduce ----
    for (int i = tid; i < HSZ; i += TPB) {
        int tok = s_hkey[i];
        if (tok >= 0) {
            float x = logits[(size_t)b * NV + tok];
            float a = s_hval[i];
            zp += __expf((x - a) * invT) - __expf(x * invT);
        }
    }
    for (int o = 16; o; o >>= 1) zp += __shfl_xor_sync(0xffffffffu, zp, o);
    if (lane == 0) s_redf[wid] = zp;
    __syncthreads();
    if (wid == 0) {
        float r = s_redf[lane];
        for (int o = 16; o; o >>= 1) r += __shfl_xor_sync(0xffffffffu, r, o);
        if (lane == 0) s_Z = r;
    }
    if (tid == 0) { s_bK = NBINS; s_bP = NBINS; s_CntB = 0; }
    __syncthreads();
    const float tpZ = tp * s_Z;

    // ---- count-hist scan: rank-K boundary bin bK + exclusive count ----
    {
        unsigned c0 = s_hist[tid*4+0], c1 = s_hist[tid*4+1], c2 = s_hist[tid*4+2], c3 = s_hist[tid*4+3];
        unsigned i0 = c0, i1 = i0+c1, i2 = i1+c2, i3 = i2+c3;
        unsigned tsum = i3, incl = tsum;
        for (int o = 1; o < 32; o <<= 1) { unsigned t = __shfl_up_sync(0xffffffffu, incl, o); if (lane >= o) incl += t; }
        if (lane == 31) s_redu[wid] = incl;
        __syncthreads();
        if (wid == 0) {
            unsigned w = s_redu[lane], wi = w;
            for (int o = 1; o < 32; o <<= 1) { unsigned t = __shfl_up_sync(0xffffffffu, wi, o); if (lane >= o) wi += t; }
            s_redu[lane] = wi - w;
        }
        __syncthreads();
        unsigned start = (incl - tsum) + s_redu[wid];
        if (start < K && start + tsum >= K) {
            if      (start + i0 >= K) { s_bK = tid*4+0; s_CntB = start; }
            else if (start + i1 >= K) { s_bK = tid*4+1; s_CntB = start + i0; }
            else if (start + i2 >= K) { s_bK = tid*4+2; s_CntB = start + i1; }
            else                      { s_bK = tid*4+3; s_CntB = start + i2; }
        }
    }
    __syncthreads();
    const unsigned bK = s_bK;

    // ---- w-hist (aliases count hist) over candidates, then scan: top-p bin bP ----
    float* wh = (float*)s_hist;
    for (int i = tid; i < NBINS; i += TPB) wh[i] = 0.0f;
    __syncthreads();
    for (unsigned i = tid; i < cntEff; i += TPB) {
        unsigned long long key = s_cand[i];
        float xp = __uint_as_float((unsigned)(key >> 32));
        int ids = (int)((HIW - xp) * hsc);
        ids = min(max(ids, 0), NBINS - 1);
        atomicAdd(&wh[ids], __expf(xp * invT));
    }
    __syncthreads();
    {
        float c0 = wh[tid*4+0], c1 = wh[tid*4+1], c2 = wh[tid*4+2], c3 = wh[tid*4+3];
        float i0 = c0, i1 = i0+c1, i2 = i1+c2, i3 = i2+c3;
        float tsum = i3, incl = tsum;
        for (int o = 1; o < 32; o <<= 1) { float t = __shfl_up_sync(0xffffffffu, incl, o); if (lane >= o) incl += t; }
        if (lane == 31) s_redf[wid] = incl;
        __syncthreads();
        if (wid == 0) {
            float w = s_redf[lane], wi = w;
            for (int o = 1; o < 32; o <<= 1) { float t = __shfl_up_sync(0xffffffffu, wi, o); if (lane >= o) wi += t; }
            s_redf[lane] = wi - w;
        }
        __syncthreads();
        float start = (incl - tsum) + s_redf[wid];
        if (start <= tpZ && start + tsum > tpZ) {
            if      (start + i0 > tpZ) { s_bP = tid*4+0; s_WexclP = start; }
            else if (start + i1 > tpZ) { s_bP = tid*4+1; s_WexclP = start + i0; }
            else if (start + i2 > tpZ) { s_bP = tid*4+2; s_WexclP = start + i1; }
            else                       { s_bP = tid*4+3; s_WexclP = start + i2; }
        }
        if (bK < NBINS && (bK >> 2) == (unsigned)tid) {
            unsigned r = bK & 3;
            s_WexclK = start + (r == 0 ? 0.f : r == 1 ? i0 : r == 2 ? i1 : i2);
        }
        if (tid == TPB-1) s_Wtot = start + tsum;
    }
    __syncthreads();

    const unsigned bP   = s_bP;
    const unsigned bcut = min(bK, bP);

    if (bcut >= NBINS) {
        if (tid == 0) { s_S = s_Wtot; s_cut = 0ull; }
        __syncthreads();
    } else {
        // gather the single boundary bin, sort it, walk exactly
        if (tid == 0) s_gcnt = 0;
        __syncthreads();
        for (unsigned i = tid; i < cntEff; i += TPB) {
            unsigned long long key = s_cand[i];
            float xp = __uint_as_float((unsigned)(key >> 32));
            int ids = (int)((HIW - xp) * hsc);
            ids = min(max(ids, 0), NBINS - 1);
            if ((unsigned)ids == bcut) {
                unsigned pos = atomicAdd(&s_gcnt, 1u);
                if (pos < GCAP) s_gath[pos] = key;
            }
        }
        __syncthreads();
        unsigned g = min(s_gcnt, (unsigned)GCAP);
        unsigned P = 2; while (P < g) P <<= 1;
        for (unsigned i = tid; i < P; i += TPB) if (i >= g) s_gath[i] = 0ull;
        __syncthreads();
        for (unsigned k = 2; k <= P; k <<= 1) {
            for (unsigned j = k >> 1; j > 0; j >>= 1) {
                for (unsigned i = tid; i < P; i += TPB) {
                    unsigned l = i ^ j;
                    if (l > i) {
                        unsigned long long a = s_gath[i], bb = s_gath[l];
                        bool desc = ((i & k) == 0);
                        if (desc ? (a < bb) : (a > bb)) { s_gath[i] = bb; s_gath[l] = a; }
                    }
                }
                __syncthreads();
            }
        }
        if (tid == 0) {
            float e = (bcut == bK) ? s_WexclK : s_WexclP;
            unsigned kmax = (bcut == bK) ? (K - s_CntB) : 0xffffffffu;
            unsigned kept = 0;
            while (kept < g && kept < kmax) {
                if (e > tpZ) break;               // exclusive cumsum > top_p*Z -> stop
                float xp = __uint_as_float((unsigned)(s_gath[kept] >> 32));
                e += __expf(xp * invT);
                kept++;
            }
            s_S = e;
            s_cut = kept ? s_gath[kept-1] : 0xffffffffffffffffull;
        }
        __syncthreads();
    }

    const float invS = 1.0f / s_S;
    const unsigned long long cut = s_cut;

    // ---- scatter kept probs (w/W_kept; Z cancels) ----
    for (unsigned i = tid; i < cntEff; i += TPB) {
        unsigned long long key = s_cand[i];
        float xp = __uint_as_float((unsigned)(key >> 32));
        int ids = (int)((HIW - xp) * hsc);
        ids = min(max(ids, 0), NBINS - 1);
        bool keep = ((unsigned)ids < bcut) || ((unsigned)ids == bcut && key >= cut);
        if (keep) {
            unsigned idx = ~(unsigned)key;
            out[(size_t)b * NV + idx] = __expf(xp * invT) * invS;
        }
    }
}

extern "C" void kernel_launch(void* const* d_in, const int* in_sizes, int n_in,
                              void* d_out, int out_size) {
    const float* logits = (const float*)d_in[0];
    const int*   toks   = (const int*)d_in[1];
    const float* pres   = (const float*)d_in[2];
    const float* freq   = (const float*)d_in[3];
    const float* temps  = (const float*)d_in[4];
    const float* topps  = (const float*)d_in[5];
    const int*   topks  = (const int*)d_in[6];
    sampler_kernel<<<NB, TPB>>>(logits, toks, pres, freq, temps, topps, topks, (float*)d_out);
}

// round 7
// speedup vs baseline: 1.8906x; 1.1630x over previous
#include <cuda_runtime.h>

#define TPB   1024
#define NB    128
#define NV    128000
#define NV4   (NV/4)
#define NL    200
#define HSZ   512
#define HMASK 511
#define NBINS 4096
#define CAP   2560
#define GCAP  512
#define HIW   7.0f
#define LB0   2.1f

__device__ __forceinline__ float hlookup(int idx, const int* hkey, const float* hval) {
    unsigned h = ((unsigned)idx * 2654435761u) >> 23;
    int k = hkey[h];
    while (k >= 0) {
        if (k == idx) return hval[h];
        h = (h + 1) & HMASK;
        k = hkey[h];
    }
    return 0.0f;
}

__global__ __launch_bounds__(TPB, 1)
void sampler_kernel(const float* __restrict__ logits,
                    const int* __restrict__ toks,
                    const float* __restrict__ presp,
                    const float* __restrict__ freqp,
                    const float* __restrict__ temps,
                    const float* __restrict__ topps,
                    const int* __restrict__ topks,
                    float* __restrict__ out)
{
    __shared__ int   s_hkey[HSZ];
    __shared__ float s_hval[HSZ];
    __shared__ unsigned long long s_cand[CAP];
    __shared__ unsigned s_hist[NBINS];                 // reused as float w-hist in stage 2
    __shared__ unsigned long long s_gath[GCAP];
    __shared__ float s_redf[32];
    __shared__ unsigned s_redu[32];
    __shared__ float s_Z, s_WexclK, s_WexclP, s_Wtot, s_S;
    __shared__ unsigned s_cnt, s_gcnt, s_bK, s_bP, s_CntB;
    __shared__ unsigned long long s_cut;

    const int tid  = threadIdx.x;
    const int lane = tid & 31;
    const int wid  = tid >> 5;
    const int b    = blockIdx.x;

    const float invT = 1.0f / temps[b];
    const float fpen = freqp[b];
    const float ppen = presp[b];
    const float tp   = topps[b];
    const int   Ksel = topks[b];
    const unsigned K = (unsigned)Ksel;

    // ---- penalty hash: token -> f*count + p ----
    for (int i = tid; i < HSZ; i += TPB) { s_hkey[i] = -1; ((int*)s_hval)[i] = 0; }
    __syncthreads();
    if (tid < NL) {
        int tok = toks[(size_t)b * NL + tid];
        unsigned h = ((unsigned)tok * 2654435761u) >> 23;
        for (;;) {
            int prev = atomicCAS(&s_hkey[h], -1, tok);
            if (prev == -1 || prev == tok) { atomicAdd((int*)&s_hval[h], 1); break; }
            h = (h + 1) & HMASK;
        }
    }
    __syncthreads();
    for (int i = tid; i < HSZ; i += TPB) {
        if (s_hkey[i] >= 0) {
            int c = ((int*)s_hval)[i];
            s_hval[i] = fpen * (float)c + ppen;
        }
    }
    __syncthreads();

    const float4* lg4 = reinterpret_cast<const float4*>(logits + (size_t)b * NV);
    float4* o4 = reinterpret_cast<float4*>(out + (size_t)b * NV);
    const float4 z4 = make_float4(0.f, 0.f, 0.f, 0.f);

    // ---- pass 1 (with rare retries): Z + zero-fill + candidate collect + count hist ----
    float LB = LB0;
    float hsc = 0.0f;
    float ztot = 0.0f;
    unsigned cntEff = 0;
    for (int att = 0; att < 4; att++) {
        hsc = (float)NBINS / (HIW - LB);
        for (int i = tid; i < NBINS; i += TPB) s_hist[i] = 0;
        if (tid == 0) s_cnt = 0;
        float z0 = 0.f, z1 = 0.f, z2 = 0.f, z3 = 0.f;
        __syncthreads();

        // candidate-path processing for one element
        #define PROC_TAIL(XV, IDX)                                                        \
            if ((XV) > LB) {                                                              \
                float a_  = hlookup((IDX), s_hkey, s_hval);                               \
                float xp_ = (XV) - a_;                                                    \
                if (xp_ > LB) {                                                           \
                    int ids_ = (int)((HIW - xp_) * hsc);                                  \
                    ids_ = min(max(ids_, 0), NBINS - 1);                                  \
                    atomicAdd(&s_hist[ids_], 1u);                                         \
                    unsigned pos_ = atomicAdd(&s_cnt, 1u);                                \
                    if (pos_ < CAP)                                                       \
                        s_cand[pos_] = ((unsigned long long)__float_as_uint(xp_) << 32)   \
                                       | (unsigned)(~(unsigned)(IDX));                    \
                }                                                                         \
            }

        int v = tid;
        // unrolled-by-4: front-batch 4 independent LDG.128 per warp iteration
        for (; v + 3*TPB < NV4; v += 4*TPB) {
            float4 x0 = lg4[v];
            float4 x1 = lg4[v +   TPB];
            float4 x2 = lg4[v + 2*TPB];
            float4 x3 = lg4[v + 3*TPB];
            if (att == 0) {
                o4[v]         = z4;
                o4[v +   TPB] = z4;
                o4[v + 2*TPB] = z4;
                o4[v + 3*TPB] = z4;
            }
            z0 += __expf(x0.x*invT) + __expf(x0.y*invT) + __expf(x0.z*invT) + __expf(x0.w*invT);
            z1 += __expf(x1.x*invT) + __expf(x1.y*invT) + __expf(x1.z*invT) + __expf(x1.w*invT);
            z2 += __expf(x2.x*invT) + __expf(x2.y*invT) + __expf(x2.z*invT) + __expf(x2.w*invT);
            z3 += __expf(x3.x*invT) + __expf(x3.y*invT) + __expf(x3.z*invT) + __expf(x3.w*invT);
            {
                int base = v * 4;
                PROC_TAIL(x0.x, base+0) PROC_TAIL(x0.y, base+1) PROC_TAIL(x0.z, base+2) PROC_TAIL(x0.w, base+3)
            }
            {
                int base = (v + TPB) * 4;
                PROC_TAIL(x1.x, base+0) PROC_TAIL(x1.y, base+1) PROC_TAIL(x1.z, base+2) PROC_TAIL(x1.w, base+3)
            }
            {
                int base = (v + 2*TPB) * 4;
                PROC_TAIL(x2.x, base+0) PROC_TAIL(x2.y, base+1) PROC_TAIL(x2.z, base+2) PROC_TAIL(x2.w, base+3)
            }
            {
                int base = (v + 3*TPB) * 4;
                PROC_TAIL(x3.x, base+0) PROC_TAIL(x3.y, base+1) PROC_TAIL(x3.z, base+2) PROC_TAIL(x3.w, base+3)
            }
        }
        for (; v < NV4; v += TPB) {
            float4 x0 = lg4[v];
            if (att == 0) o4[v] = z4;
            z0 += __expf(x0.x*invT) + __expf(x0.y*invT) + __expf(x0.z*invT) + __expf(x0.w*invT);
            int base = v * 4;
            PROC_TAIL(x0.x, base+0) PROC_TAIL(x0.y, base+1) PROC_TAIL(x0.z, base+2) PROC_TAIL(x0.w, base+3)
        }
        ztot = (z0 + z1) + (z2 + z3);
        __syncthreads();
        unsigned cnt = s_cnt;
        if (cnt >= K && cnt <= CAP) { cntEff = cnt; break; }
        if (cnt < K) {                           // far too few: widen (shouldn't happen)
            if (att < 3) { LB -= 1.0f; continue; }
            cntEff = min(cnt, (unsigned)CAP); break;
        }
        // overflow: find bin prefix holding >= K via hist, recollect filtered (L2-resident)
        if (tid == 0) s_bK = NBINS;
        __syncthreads();
        {
            unsigned c0 = s_hist[tid*4+0], c1 = s_hist[tid*4+1], c2 = s_hist[tid*4+2], c3 = s_hist[tid*4+3];
            unsigned i0 = c0, i1 = i0+c1, i2 = i1+c2, i3 = i2+c3;
            unsigned tsum = i3, incl = tsum;
            for (int o = 1; o < 32; o <<= 1) { unsigned t = __shfl_up_sync(0xffffffffu, incl, o); if (lane >= o) incl += t; }
            if (lane == 31) s_redu[wid] = incl;
            __syncthreads();
            if (wid == 0) {
                unsigned w = s_redu[lane], wi = w;
                for (int o = 1; o < 32; o <<= 1) { unsigned t = __shfl_up_sync(0xffffffffu, wi, o); if (lane >= o) wi += t; }
                s_redu[lane] = wi - w;
            }
            __syncthreads();
            unsigned start = (incl - tsum) + s_redu[wid];
            if (start < K && start + tsum >= K) {
                if      (start + i0 >= K) s_bK = tid*4+0;
                else if (start + i1 >= K) s_bK = tid*4+1;
                else if (start + i2 >= K) s_bK = tid*4+2;
                else                      s_bK = tid*4+3;
            }
        }
        __syncthreads();
        unsigned bstar = s_bK;
        if (tid == 0) s_cnt = 0;
        __syncthreads();
        for (int v2 = tid; v2 < NV4; v2 += TPB) {
            float4 x = lg4[v2];
            int base = v2 * 4;
            float xs[4] = {x.x, x.y, x.z, x.w};
            #pragma unroll
            for (int c = 0; c < 4; c++) {
                float xv = xs[c];
                if (xv > LB) {
                    float a  = hlookup(base + c, s_hkey, s_hval);
                    float xp = xv - a;
                    if (xp > LB) {
                        int ids = (int)((HIW - xp) * hsc);
                        ids = min(max(ids, 0), NBINS - 1);
                        if ((unsigned)ids <= bstar) {
                            unsigned pos = atomicAdd(&s_cnt, 1u);
                            if (pos < CAP)
                                s_cand[pos] = ((unsigned long long)__float_as_uint(xp) << 32)
                                              | (unsigned)(~(unsigned)(base + c));
                        }
                    }
                }
            }
        }
        __syncthreads();
        cntEff = min(s_cnt, (unsigned)CAP);
        break;
    }

    // ---- Z fixup (penalized tokens) + reduce ----
    for (int i = tid; i < HSZ; i += TPB) {
        int tok = s_hkey[i];
        if (tok >= 0) {
            float x = logits[(size_t)b * NV + tok];
            float a = s_hval[i];
            ztot += __expf((x - a) * invT) - __expf(x * invT);
        }
    }
    for (int o = 16; o; o >>= 1) ztot += __shfl_xor_sync(0xffffffffu, ztot, o);
    if (lane == 0) s_redf[wid] = ztot;
    __syncthreads();
    if (wid == 0) {
        float r = s_redf[lane];
        for (int o = 16; o; o >>= 1) r += __shfl_xor_sync(0xffffffffu, r, o);
        if (lane == 0) s_Z = r;
    }
    if (tid == 0) { s_bK = NBINS; s_bP = NBINS; s_CntB = 0; }
    __syncthreads();
    const float tpZ = tp * s_Z;

    // ---- count-hist scan: rank-K boundary bin bK + exclusive count ----
    {
        unsigned c0 = s_hist[tid*4+0], c1 = s_hist[tid*4+1], c2 = s_hist[tid*4+2], c3 = s_hist[tid*4+3];
        unsigned i0 = c0, i1 = i0+c1, i2 = i1+c2, i3 = i2+c3;
        unsigned tsum = i3, incl = tsum;
        for (int o = 1; o < 32; o <<= 1) { unsigned t = __shfl_up_sync(0xffffffffu, incl, o); if (lane >= o) incl += t; }
        if (lane == 31) s_redu[wid] = incl;
        __syncthreads();
        if (wid == 0) {
            unsigned w = s_redu[lane], wi = w;
            for (int o = 1; o < 32; o <<= 1) { unsigned t = __shfl_up_sync(0xffffffffu, wi, o); if (lane >= o) wi += t; }
            s_redu[lane] = wi - w;
        }
        __syncthreads();
        unsigned start = (incl - tsum) + s_redu[wid];
        if (start < K && start + tsum >= K) {
            if      (start + i0 >= K) { s_bK = tid*4+0; s_CntB = start; }
            else if (start + i1 >= K) { s_bK = tid*4+1; s_CntB = start + i0; }
            else if (start + i2 >= K) { s_bK = tid*4+2; s_CntB = start + i1; }
            else                      { s_bK = tid*4+3; s_CntB = start + i2; }
        }
    }
    __syncthreads();
    const unsigned bK = s_bK;

    // ---- w-hist (aliases count hist) over candidates, then scan: top-p bin bP ----
    float* wh = (float*)s_hist;
    for (int i = tid; i < NBINS; i += TPB) wh[i] = 0.0f;
    __syncthreads();
    for (unsigned i = tid; i < cntEff; i += TPB) {
        unsigned long long key = s_cand[i];
        float xp = __uint_as_float((unsigned)(key >> 32));
        int ids = (int)((HIW - xp) * hsc);
        ids = min(max(ids, 0), NBINS - 1);
        atomicAdd(&wh[ids], __expf(xp * invT));
    }
    __syncthreads();
    {
        float c0 = wh[tid*4+0], c1 = wh[tid*4+1], c2 = wh[tid*4+2], c3 = wh[tid*4+3];
        float i0 = c0, i1 = i0+c1, i2 = i1+c2, i3 = i2+c3;
        float tsum = i3, incl = tsum;
        for (int o = 1; o < 32; o <<= 1) { float t = __shfl_up_sync(0xffffffffu, incl, o); if (lane >= o) incl += t; }
        if (lane == 31) s_redf[wid] = incl;
        __syncthreads();
        if (wid == 0) {
            float w = s_redf[lane], wi = w;
            for (int o = 1; o < 32; o <<= 1) { float t = __shfl_up_sync(0xffffffffu, wi, o); if (lane >= o) wi += t; }
            s_redf[lane] = wi - w;
        }
        __syncthreads();
        float start = (incl - tsum) + s_redf[wid];
        if (start <= tpZ && start + tsum > tpZ) {
            if      (start + i0 > tpZ) { s_bP = tid*4+0; s_WexclP = start; }
            else if (start + i1 > tpZ) { s_bP = tid*4+1; s_WexclP = start + i0; }
            else if (start + i2 > tpZ) { s_bP = tid*4+2; s_WexclP = start + i1; }
            else                       { s_bP = tid*4+3; s_WexclP = start + i2; }
        }
        if (bK < NBINS && (bK >> 2) == (unsigned)tid) {
            unsigned r = bK & 3;
            s_WexclK = start + (r == 0 ? 0.f : r == 1 ? i0 : r == 2 ? i1 : i2);
        }
        if (tid == TPB-1) s_Wtot = start + tsum;
    }
    __syncthreads();

    const unsigned bP   = s_bP;
    const unsigned bcut = min(bK, bP);

    if (bcut >= NBINS) {
        if (tid == 0) { s_S = s_Wtot; s_cut = 0ull; }
        __syncthreads();
    } else {
        // gather the single boundary bin, sort it, walk exactly
        if (tid == 0) s_gcnt = 0;
        __syncthreads();
        for (unsigned i = tid; i < cntEff; i += TPB) {
            unsigned long long key = s_cand[i];
            float xp = __uint_as_float((unsigned)(key >> 32));
            int ids = (int)((HIW - xp) * hsc);
            ids = min(max(ids, 0), NBINS - 1);
            if ((unsigned)ids == bcut) {
                unsigned pos = atomicAdd(&s_gcnt, 1u);
                if (pos < GCAP) s_gath[pos] = key;
            }
        }
        __syncthreads();
        unsigned g = min(s_gcnt, (unsigned)GCAP);
        unsigned P = 2; while (P < g) P <<= 1;
        for (unsigned i = tid; i < P; i += TPB) if (i >= g) s_gath[i] = 0ull;
        __syncthreads();
        for (unsigned k = 2; k <= P; k <<= 1) {
            for (unsigned j = k >> 1; j > 0; j >>= 1) {
                for (unsigned i = tid; i < P; i += TPB) {
                    unsigned l = i ^ j;
                    if (l > i) {
                        unsigned long long a = s_gath[i], bb = s_gath[l];
                        bool desc = ((i & k) == 0);
                        if (desc ? (a < bb) : (a > bb)) { s_gath[i] = bb; s_gath[l] = a; }
                    }
                }
                __syncthreads();
            }
        }
        if (tid == 0) {
            float e = (bcut == bK) ? s_WexclK : s_WexclP;
            unsigned kmax = (bcut == bK) ? (K - s_CntB) : 0xffffffffu;
            unsigned kept = 0;
            while (kept < g && kept < kmax) {
                if (e > tpZ) break;               // exclusive cumsum > top_p*Z -> stop
                float xp = __uint_as_float((unsigned)(s_gath[kept] >> 32));
                e += __expf(xp * invT);
                kept++;
            }
            s_S = e;
            s_cut = kept ? s_gath[kept-1] : 0xffffffffffffffffull;
        }
        __syncthreads();
    }

    const float invS = 1.0f / s_S;
    const unsigned long long cut = s_cut;

    // ---- scatter kept probs (w/W_kept; Z cancels) ----
    for (unsigned i = tid; i < cntEff; i += TPB) {
        unsigned long long key = s_cand[i];
        float xp = __uint_as_float((unsigned)(key >> 32));
        int ids = (int)((HIW - xp) * hsc);
        ids = min(max(ids, 0), NBINS - 1);
        bool keep = ((unsigned)ids < bcut) || ((unsigned)ids == bcut && key >= cut);
        if (keep) {
            unsigned idx = ~(unsigned)key;
            out[(size_t)b * NV + idx] = __expf(xp * invT) * invS;
        }
    }
    #undef PROC_TAIL
}

extern "C" void kernel_launch(void* const* d_in, const int* in_sizes, int n_in,
                              void* d_out, int out_size) {
    const float* logits = (const float*)d_in[0];
    const int*   toks   = (const int*)d_in[1];
    const float* pres   = (const float*)d_in[2];
    const float* freq   = (const float*)d_in[3];
    const float* temps  = (const float*)d_in[4];
    const float* topps  = (const float*)d_in[5];
    const int*   topks  = (const int*)d_in[6];
    sampler_kernel<<<NB, TPB>>>(logits, toks, pres, freq, temps, topps, topks, (float*)d_out);
}

// round 8
// speedup vs baseline: 1.9706x; 1.0423x over previous
#include <cuda_runtime.h>

#define TPB   1024
#define NB    128
#define NV    128000
#define NV4   (NV/4)
#define NST   ((NV4 + TPB - 1) / TPB)
#define NL    200
#define HSZ   512
#define HMASK 511
#define NBINS 4096
#define CAP   2560
#define GCAP  512
#define HIW   7.0f
#define LB0   2.1f
#define STAGES 4
#define SMEM_DYN (STAGES * TPB * 16)

__device__ __forceinline__ float hlookup(int idx, const int* hkey, const float* hval) {
    unsigned h = ((unsigned)idx * 2654435761u) >> 23;
    int k = hkey[h];
    while (k >= 0) {
        if (k == idx) return hval[h];
        h = (h + 1) & HMASK;
        k = hkey[h];
    }
    return 0.0f;
}

__global__ __launch_bounds__(TPB, 1)
void sampler_kernel(const float* __restrict__ logits,
                    const int* __restrict__ toks,
                    const float* __restrict__ presp,
                    const float* __restrict__ freqp,
                    const float* __restrict__ temps,
                    const float* __restrict__ topps,
                    const int* __restrict__ topks,
                    float* __restrict__ out)
{
    extern __shared__ float4 s_tile[];                 // STAGES * TPB float4 ring
    __shared__ int   s_hkey[HSZ];
    __shared__ float s_hval[HSZ];
    __shared__ unsigned long long s_cand[CAP];
    __shared__ unsigned s_hist[NBINS];                 // reused as float w-hist in stage 2
    __shared__ unsigned long long s_gath[GCAP];
    __shared__ float s_redf[32];
    __shared__ unsigned s_redu[32];
    __shared__ float s_Z, s_WexclK, s_WexclP, s_Wtot, s_S;
    __shared__ unsigned s_cnt, s_gcnt, s_bK, s_bP, s_CntB;
    __shared__ unsigned long long s_cut;

    const int tid  = threadIdx.x;
    const int lane = tid & 31;
    const int wid  = tid >> 5;
    const int b    = blockIdx.x;

    const float invT = 1.0f / temps[b];
    const float fpen = freqp[b];
    const float ppen = presp[b];
    const float tp   = topps[b];
    const int   Ksel = topks[b];
    const unsigned K = (unsigned)Ksel;

    // ---- penalty hash: token -> f*count + p ----
    for (int i = tid; i < HSZ; i += TPB) { s_hkey[i] = -1; ((int*)s_hval)[i] = 0; }
    __syncthreads();
    if (tid < NL) {
        int tok = toks[(size_t)b * NL + tid];
        unsigned h = ((unsigned)tok * 2654435761u) >> 23;
        for (;;) {
            int prev = atomicCAS(&s_hkey[h], -1, tok);
            if (prev == -1 || prev == tok) { atomicAdd((int*)&s_hval[h], 1); break; }
            h = (h + 1) & HMASK;
        }
    }
    __syncthreads();
    for (int i = tid; i < HSZ; i += TPB) {
        if (s_hkey[i] >= 0) {
            int c = ((int*)s_hval)[i];
            s_hval[i] = fpen * (float)c + ppen;
        }
    }
    __syncthreads();

    const float4* lg4 = reinterpret_cast<const float4*>(logits + (size_t)b * NV);
    float4* o4 = reinterpret_cast<float4*>(out + (size_t)b * NV);
    const float4 z4 = make_float4(0.f, 0.f, 0.f, 0.f);
    unsigned stbase = (unsigned)__cvta_generic_to_shared(s_tile);

    // ---- pass 1 (with rare retries): Z + zero-fill + candidate collect + count hist ----
    float LB = LB0;
    float hsc = 0.0f;
    float ztot = 0.0f;
    unsigned cntEff = 0;

    #define PROC_TAIL(XV, IDX)                                                        \
        if ((XV) > LB) {                                                              \
            float a_  = hlookup((IDX), s_hkey, s_hval);                               \
            float xp_ = (XV) - a_;                                                    \
            if (xp_ > LB) {                                                           \
                int ids_ = (int)((HIW - xp_) * hsc);                                  \
                ids_ = min(max(ids_, 0), NBINS - 1);                                  \
                atomicAdd(&s_hist[ids_], 1u);                                         \
                unsigned pos_ = atomicAdd(&s_cnt, 1u);                                \
                if (pos_ < CAP)                                                       \
                    s_cand[pos_] = ((unsigned long long)__float_as_uint(xp_) << 32)   \
                                   | (unsigned)(~(unsigned)(IDX));                    \
            }                                                                         \
        }

    for (int att = 0; att < 4; att++) {
        hsc = (float)NBINS / (HIW - LB);
        for (int i = tid; i < NBINS; i += TPB) s_hist[i] = 0;
        if (tid == 0) s_cnt = 0;
        float z0 = 0.f, z1 = 0.f;
        __syncthreads();

        if (att == 0) {
            // --- cp.async 4-stage pipeline; each thread consumes only its own slot ---
            #pragma unroll
            for (int s = 0; s < STAGES - 1; s++) {
                int v = s * TPB + tid;
                if (v < NV4) {
                    unsigned dst = stbase + (unsigned)(((s & (STAGES-1)) * TPB + tid) * 16);
                    asm volatile("cp.async.cg.shared.global [%0], [%1], 16;"
                                 :: "r"(dst), "l"(lg4 + v) : "memory");
                }
                asm volatile("cp.async.commit_group;" ::: "memory");
            }
            for (int s = 0; s < NST; s++) {
                int vn = (s + STAGES - 1) * TPB + tid;
                if (vn < NV4) {
                    unsigned dst = stbase + (unsigned)(((((s + STAGES - 1) & (STAGES-1))) * TPB + tid) * 16);
                    asm volatile("cp.async.cg.shared.global [%0], [%1], 16;"
                                 :: "r"(dst), "l"(lg4 + vn) : "memory");
                }
                asm volatile("cp.async.commit_group;" ::: "memory");
                asm volatile("cp.async.wait_group %0;" :: "n"(STAGES-1) : "memory");
                int v = s * TPB + tid;
                if (v < NV4) {
                    float4 x0 = s_tile[(s & (STAGES-1)) * TPB + tid];
                    o4[v] = z4;                      // zero-fill fused
                    z0 += __expf(x0.x*invT) + __expf(x0.y*invT);
                    z1 += __expf(x0.z*invT) + __expf(x0.w*invT);
                    int base = v * 4;
                    PROC_TAIL(x0.x, base+0) PROC_TAIL(x0.y, base+1)
                    PROC_TAIL(x0.z, base+2) PROC_TAIL(x0.w, base+3)
                }
            }
            asm volatile("cp.async.wait_group 0;" ::: "memory");
        } else {
            for (int v = tid; v < NV4; v += TPB) {   // rare retry: L2-resident
                float4 x0 = lg4[v];
                z0 += __expf(x0.x*invT) + __expf(x0.y*invT);
                z1 += __expf(x0.z*invT) + __expf(x0.w*invT);
                int base = v * 4;
                PROC_TAIL(x0.x, base+0) PROC_TAIL(x0.y, base+1)
                PROC_TAIL(x0.z, base+2) PROC_TAIL(x0.w, base+3)
            }
        }
        ztot = z0 + z1;
        __syncthreads();
        unsigned cnt = s_cnt;
        if (cnt >= K && cnt <= CAP) { cntEff = cnt; break; }
        if (cnt < K) {                           // far too few: widen (shouldn't happen)
            if (att < 3) { LB -= 1.0f; continue; }
            cntEff = min(cnt, (unsigned)CAP); break;
        }
        // overflow: find bin prefix holding >= K via hist, recollect filtered (L2-resident)
        if (tid == 0) s_bK = NBINS;
        __syncthreads();
        {
            unsigned c0 = s_hist[tid*4+0], c1 = s_hist[tid*4+1], c2 = s_hist[tid*4+2], c3 = s_hist[tid*4+3];
            unsigned i0 = c0, i1 = i0+c1, i2 = i1+c2, i3 = i2+c3;
            unsigned tsum = i3, incl = tsum;
            for (int o = 1; o < 32; o <<= 1) { unsigned t = __shfl_up_sync(0xffffffffu, incl, o); if (lane >= o) incl += t; }
            if (lane == 31) s_redu[wid] = incl;
            __syncthreads();
            if (wid == 0) {
                unsigned w = s_redu[lane], wi = w;
                for (int o = 1; o < 32; o <<= 1) { unsigned t = __shfl_up_sync(0xffffffffu, wi, o); if (lane >= o) wi += t; }
                s_redu[lane] = wi - w;
            }
            __syncthreads();
            unsigned start = (incl - tsum) + s_redu[wid];
            if (start < K && start + tsum >= K) {
                if      (start + i0 >= K) s_bK = tid*4+0;
                else if (start + i1 >= K) s_bK = tid*4+1;
                else if (start + i2 >= K) s_bK = tid*4+2;
                else                      s_bK = tid*4+3;
            }
        }
        __syncthreads();
        unsigned bstar = s_bK;
        if (tid == 0) s_cnt = 0;
        __syncthreads();
        for (int v2 = tid; v2 < NV4; v2 += TPB) {
            float4 x = lg4[v2];
            int base = v2 * 4;
            float xs[4] = {x.x, x.y, x.z, x.w};
            #pragma unroll
            for (int c = 0; c < 4; c++) {
                float xv = xs[c];
                if (xv > LB) {
                    float a  = hlookup(base + c, s_hkey, s_hval);
                    float xp = xv - a;
                    if (xp > LB) {
                        int ids = (int)((HIW - xp) * hsc);
                        ids = min(max(ids, 0), NBINS - 1);
                        if ((unsigned)ids <= bstar) {
                            unsigned pos = atomicAdd(&s_cnt, 1u);
                            if (pos < CAP)
                                s_cand[pos] = ((unsigned long long)__float_as_uint(xp) << 32)
                                              | (unsigned)(~(unsigned)(base + c));
                        }
                    }
                }
            }
        }
        __syncthreads();
        cntEff = min(s_cnt, (unsigned)CAP);
        break;
    }

    // ---- Z fixup (penalized tokens) + reduce ----
    for (int i = tid; i < HSZ; i += TPB) {
        int tok = s_hkey[i];
        if (tok >= 0) {
            float x = logits[(size_t)b * NV + tok];
            float a = s_hval[i];
            ztot += __expf((x - a) * invT) - __expf(x * invT);
        }
    }
    for (int o = 16; o; o >>= 1) ztot += __shfl_xor_sync(0xffffffffu, ztot, o);
    if (lane == 0) s_redf[wid] = ztot;
    __syncthreads();
    if (wid == 0) {
        float r = s_redf[lane];
        for (int o = 16; o; o >>= 1) r += __shfl_xor_sync(0xffffffffu, r, o);
        if (lane == 0) s_Z = r;
    }
    if (tid == 0) { s_bK = NBINS; s_bP = NBINS; s_CntB = 0; }
    __syncthreads();
    const float tpZ = tp * s_Z;

    // ---- count-hist scan: rank-K boundary bin bK + exclusive count ----
    {
        unsigned c0 = s_hist[tid*4+0], c1 = s_hist[tid*4+1], c2 = s_hist[tid*4+2], c3 = s_hist[tid*4+3];
        unsigned i0 = c0, i1 = i0+c1, i2 = i1+c2, i3 = i2+c3;
        unsigned tsum = i3, incl = tsum;
        for (int o = 1; o < 32; o <<= 1) { unsigned t = __shfl_up_sync(0xffffffffu, incl, o); if (lane >= o) incl += t; }
        if (lane == 31) s_redu[wid] = incl;
        __syncthreads();
        if (wid == 0) {
            unsigned w = s_redu[lane], wi = w;
            for (int o = 1; o < 32; o <<= 1) { unsigned t = __shfl_up_sync(0xffffffffu, wi, o); if (lane >= o) wi += t; }
            s_redu[lane] = wi - w;
        }
        __syncthreads();
        unsigned start = (incl - tsum) + s_redu[wid];
        if (start < K && start + tsum >= K) {
            if      (start + i0 >= K) { s_bK = tid*4+0; s_CntB = start; }
            else if (start + i1 >= K) { s_bK = tid*4+1; s_CntB = start + i0; }
            else if (start + i2 >= K) { s_bK = tid*4+2; s_CntB = start + i1; }
            else                      { s_bK = tid*4+3; s_CntB = start + i2; }
        }
    }
    __syncthreads();
    const unsigned bK = s_bK;

    // ---- w-hist (aliases count hist) over candidates, then scan: top-p bin bP ----
    float* wh = (float*)s_hist;
    for (int i = tid; i < NBINS; i += TPB) wh[i] = 0.0f;
    __syncthreads();
    for (unsigned i = tid; i < cntEff; i += TPB) {
        unsigned long long key = s_cand[i];
        float xp = __uint_as_float((unsigned)(key >> 32));
        int ids = (int)((HIW - xp) * hsc);
        ids = min(max(ids, 0), NBINS - 1);
        atomicAdd(&wh[ids], __expf(xp * invT));
    }
    __syncthreads();
    {
        float c0 = wh[tid*4+0], c1 = wh[tid*4+1], c2 = wh[tid*4+2], c3 = wh[tid*4+3];
        float i0 = c0, i1 = i0+c1, i2 = i1+c2, i3 = i2+c3;
        float tsum = i3, incl = tsum;
        for (int o = 1; o < 32; o <<= 1) { float t = __shfl_up_sync(0xffffffffu, incl, o); if (lane >= o) incl += t; }
        if (lane == 31) s_redf[wid] = incl;
        __syncthreads();
        if (wid == 0) {
            float w = s_redf[lane], wi = w;
            for (int o = 1; o < 32; o <<= 1) { float t = __shfl_up_sync(0xffffffffu, wi, o); if (lane >= o) wi += t; }
            s_redf[lane] = wi - w;
        }
        __syncthreads();
        float start = (incl - tsum) + s_redf[wid];
        if (start <= tpZ && start + tsum > tpZ) {
            if      (start + i0 > tpZ) { s_bP = tid*4+0; s_WexclP = start; }
            else if (start + i1 > tpZ) { s_bP = tid*4+1; s_WexclP = start + i0; }
            else if (start + i2 > tpZ) { s_bP = tid*4+2; s_WexclP = start + i1; }
            else                       { s_bP = tid*4+3; s_WexclP = start + i2; }
        }
        if (bK < NBINS && (bK >> 2) == (unsigned)tid) {
            unsigned r = bK & 3;
            s_WexclK = start + (r == 0 ? 0.f : r == 1 ? i0 : r == 2 ? i1 : i2);
        }
        if (tid == TPB-1) s_Wtot = start + tsum;
    }
    __syncthreads();

    const unsigned bP   = s_bP;
    const unsigned bcut = min(bK, bP);

    if (bcut >= NBINS) {
        if (tid == 0) { s_S = s_Wtot; s_cut = 0ull; }
        __syncthreads();
    } else {
        // gather the single boundary bin, sort it, walk exactly
        if (tid == 0) s_gcnt = 0;
        __syncthreads();
        for (unsigned i = tid; i < cntEff; i += TPB) {
            unsigned long long key = s_cand[i];
            float xp = __uint_as_float((unsigned)(key >> 32));
            int ids = (int)((HIW - xp) * hsc);
            ids = min(max(ids, 0), NBINS - 1);
            if ((unsigned)ids == bcut) {
                unsigned pos = atomicAdd(&s_gcnt, 1u);
                if (pos < GCAP) s_gath[pos] = key;
            }
        }
        __syncthreads();
        unsigned g = min(s_gcnt, (unsigned)GCAP);
        unsigned P = 2; while (P < g) P <<= 1;
        for (unsigned i = tid; i < P; i += TPB) if (i >= g) s_gath[i] = 0ull;
        __syncthreads();
        for (unsigned k = 2; k <= P; k <<= 1) {
            for (unsigned j = k >> 1; j > 0; j >>= 1) {
                for (unsigned i = tid; i < P; i += TPB) {
                    unsigned l = i ^ j;
                    if (l > i) {
                        unsigned long long a = s_gath[i], bb = s_gath[l];
                        bool desc = ((i & k) == 0);
                        if (desc ? (a < bb) : (a > bb)) { s_gath[i] = bb; s_gath[l] = a; }
                    }
                }
                __syncthreads();
            }
        }
        if (tid == 0) {
            float e = (bcut == bK) ? s_WexclK : s_WexclP;
            unsigned kmax = (bcut == bK) ? (K - s_CntB) : 0xffffffffu;
            unsigned kept = 0;
            while (kept < g && kept < kmax) {
                if (e > tpZ) break;               // exclusive cumsum > top_p*Z -> stop
                float xp = __uint_as_float((unsigned)(s_gath[kept] >> 32));
                e += __expf(xp * invT);
                kept++;
            }
            s_S = e;
            s_cut = kept ? s_gath[kept-1] : 0xffffffffffffffffull;
        }
        __syncthreads();
    }

    const float invS = 1.0f / s_S;
    const unsigned long long cut = s_cut;

    // ---- scatter kept probs (w/W_kept; Z cancels) ----
    for (unsigned i = tid; i < cntEff; i += TPB) {
        unsigned long long key = s_cand[i];
        float xp = __uint_as_float((unsigned)(key >> 32));
        int ids = (int)((HIW - xp) * hsc);
        ids = min(max(ids, 0), NBINS - 1);
        bool keep = ((unsigned)ids < bcut) || ((unsigned)ids == bcut && key >= cut);
        if (keep) {
            unsigned idx = ~(unsigned)key;
            out[(size_t)b * NV + idx] = __expf(xp * invT) * invS;
        }
    }
    #undef PROC_TAIL
}

extern "C" void kernel_launch(void* const* d_in, const int* in_sizes, int n_in,
                              void* d_out, int out_size) {
    const float* logits = (const float*)d_in[0];
    const int*   toks   = (const int*)d_in[1];
    const float* pres   = (const float*)d_in[2];
    const float* freq   = (const float*)d_in[3];
    const float* temps  = (const float*)d_in[4];
    const float* topps  = (const float*)d_in[5];
    const int*   topks  = (const int*)d_in[6];
    cudaFuncSetAttribute(sampler_kernel, cudaFuncAttributeMaxDynamicSharedMemorySize, SMEM_DYN);
    sampler_kernel<<<NB, TPB, SMEM_DYN>>>(logits, toks, pres, freq, temps, topps, topks, (float*)d_out);
}